// round 3
// baseline (speedup 1.0000x reference)
#include <cuda_runtime.h>
#include <cuda_bf16.h>

// Inputs (metadata order):
//  0: user_embeddings   [500000, 128] f32
//  1: event_embeddings  [100000, 128] f32
//  2: pos_user_idx      [P] i32
//  3: pos_event_idx     [P] i32
//  4: neg_user_idx      [P] i32
//  5: neg_event_idx     [P] i32
//  6: W                 [1, 129] f32
//  7: b                 [1] f32
// Output: [2, P] f32  (pos scores then neg scores)

#define EPS 1e-8f

__global__ __launch_bounds__(256) void uip_score_kernel(
    const float* __restrict__ users,
    const float* __restrict__ events,
    const int*   __restrict__ pu,
    const int*   __restrict__ pe,
    const int*   __restrict__ nu,
    const int*   __restrict__ ne,
    const float* __restrict__ W,
    const float* __restrict__ bb,
    float*       __restrict__ out,
    int P)
{
    const int gw   = (int)((blockIdx.x * 256u + threadIdx.x) >> 5);  // global warp = pair id
    const int lane = threadIdx.x & 31;
    const int total = 2 * P;
    if (gw >= total) return;

    int ui, ei;
    if (gw < P) {
        ui = __ldg(pu + gw);
        ei = __ldg(pe + gw);
    } else {
        ui = __ldg(nu + (gw - P));
        ei = __ldg(ne + (gw - P));
    }

    // One warp per pair: lane l owns elements [4l, 4l+4) of the 128-dim row.
    // Each row load is one fully coalesced 512B (4-sector) access.
    const float4 u4 = __ldg(reinterpret_cast<const float4*>(users)  + (size_t)ui * 32 + lane);
    const float4 e4 = __ldg(reinterpret_cast<const float4*>(events) + (size_t)ei * 32 + lane);
    const float4 w4 = __ldg(reinterpret_cast<const float4*>(W) + lane);

    float ue = u4.x * e4.x + u4.y * e4.y + u4.z * e4.z + u4.w * e4.w;
    float uu = u4.x * u4.x + u4.y * u4.y + u4.z * u4.z + u4.w * u4.w;
    float ee = e4.x * e4.x + e4.y * e4.y + e4.z * e4.z + e4.w * e4.w;
    float uw = u4.x * w4.x + u4.y * w4.y + u4.z * w4.z + u4.w * w4.w;

    #pragma unroll
    for (int off = 16; off > 0; off >>= 1) {
        ue += __shfl_xor_sync(0xffffffffu, ue, off);
        uu += __shfl_xor_sync(0xffffffffu, uu, off);
        ee += __shfl_xor_sync(0xffffffffu, ee, off);
        uw += __shfl_xor_sync(0xffffffffu, uw, off);
    }

    if (lane == 0) {
        const float un  = fmaxf(sqrtf(uu), EPS);
        const float en  = fmaxf(sqrtf(ee), EPS);
        const float sim = ue / (un * en);
        out[gw] = fmaf(sim, __ldg(W + 128), uw + __ldg(bb));
    }
}

extern "C" void kernel_launch(void* const* d_in, const int* in_sizes, int n_in,
                              void* d_out, int out_size)
{
    const float* users  = (const float*)d_in[0];
    const float* events = (const float*)d_in[1];
    const int*   pu     = (const int*)d_in[2];
    const int*   pe     = (const int*)d_in[3];
    const int*   nu     = (const int*)d_in[4];
    const int*   ne     = (const int*)d_in[5];
    const float* W      = (const float*)d_in[6];
    const float* bb     = (const float*)d_in[7];
    float*       out    = (float*)d_out;

    const int P = in_sizes[2];               // 524288 pairs
    const int total_warps = 2 * P;           // one warp per (pair, pos/neg)
    const int threads = 256;                 // 8 warps per block
    const int blocks = (total_warps * 32 + threads - 1) / threads;

    uip_score_kernel<<<blocks, threads>>>(users, events, pu, pe, nu, ne, W, bb, out, P);
}

// round 5
// speedup vs baseline: 1.4304x; 1.4304x over previous
#include <cuda_runtime.h>
#include <cuda_bf16.h>

// Inputs (metadata order):
//  0: user_embeddings   [500000, 128] f32
//  1: event_embeddings  [100000, 128] f32
//  2: pos_user_idx      [P] i32
//  3: pos_event_idx     [P] i32
//  4: neg_user_idx      [P] i32
//  5: neg_event_idx     [P] i32
//  6: W                 [1, 129] f32
//  7: b                 [1] f32
// Output: [2, P] f32  (pos scores then neg scores)

#define EPS 1e-8f
#define NUM_SMS 148
#define BLOCKS_PER_SM 4
#define THREADS 256
#define WARPS_PER_BLOCK (THREADS / 32)

// 8 lanes cooperate per pair; 4 pairs per warp.
__global__ __launch_bounds__(THREADS, BLOCKS_PER_SM) void uip_score_kernel(
    const float* __restrict__ users,
    const float* __restrict__ events,
    const int*   __restrict__ pu,
    const int*   __restrict__ pe,
    const int*   __restrict__ nu,
    const int*   __restrict__ ne,
    const float* __restrict__ W,
    const float* __restrict__ bb,
    float*       __restrict__ out,
    int P)
{
    const int lane = threadIdx.x & 31;
    const int sub  = lane & 7;     // position within 8-lane pair group
    const int wid  = blockIdx.x * WARPS_PER_BLOCK + (threadIdx.x >> 5);
    const int nw   = gridDim.x * WARPS_PER_BLOCK;
    const int total = 2 * P;       // total pairs (pos then neg)
    const int grp  = lane >> 3;    // 0..3: which pair within the warp

    // Per-warp invariants in registers: this lane's W slice (16 elems), W[128], bias.
    float4 w0 = __ldg(reinterpret_cast<const float4*>(W) + sub * 4 + 0);
    float4 w1 = __ldg(reinterpret_cast<const float4*>(W) + sub * 4 + 1);
    float4 w2 = __ldg(reinterpret_cast<const float4*>(W) + sub * 4 + 2);
    float4 w3 = __ldg(reinterpret_cast<const float4*>(W) + sub * 4 + 3);
    const float wSim = __ldg(W + 128);
    const float bias = __ldg(bb);

    const float4* u_tab = reinterpret_cast<const float4*>(users);
    const float4* e_tab = reinterpret_cast<const float4*>(events);

    // Each warp-iteration processes 4 pairs: p = i*4 + grp
    const int n_iters = (total + 3) >> 2;   // total is 2^20, divisible by 4
    for (int i = wid; i < n_iters; i += nw) {
        const int p = i * 4 + grp;
        // total divisible by 4 in practice; guard anyway (inactive lanes still shuffle)
        const bool active = (p < total);

        int ui = 0, ei = 0;
        if (active) {
            if (p < P) { ui = __ldg(pu + p);     ei = __ldg(pe + p); }
            else       { ui = __ldg(nu + p - P); ei = __ldg(ne + p - P); }
        }

        const float4* urow = u_tab + (size_t)ui * 32 + sub * 4;
        const float4* erow = e_tab + (size_t)ei * 32 + sub * 4;

        // 8 independent loads in flight per lane (MLP=8).
        // User table (256MB, mostly DRAM): streaming hint -> don't pollute L2.
        // Event table (51MB, fits L2): default caching -> stays resident.
        const float4 u0 = __ldcs(urow + 0);
        const float4 u1 = __ldcs(urow + 1);
        const float4 u2 = __ldcs(urow + 2);
        const float4 u3 = __ldcs(urow + 3);
        const float4 e0 = __ldg(erow + 0);
        const float4 e1 = __ldg(erow + 1);
        const float4 e2 = __ldg(erow + 2);
        const float4 e3 = __ldg(erow + 3);

        float ue, uu, ee, uw;
        ue  = u0.x*e0.x + u0.y*e0.y + u0.z*e0.z + u0.w*e0.w;
        ue += u1.x*e1.x + u1.y*e1.y + u1.z*e1.z + u1.w*e1.w;
        ue += u2.x*e2.x + u2.y*e2.y + u2.z*e2.z + u2.w*e2.w;
        ue += u3.x*e3.x + u3.y*e3.y + u3.z*e3.z + u3.w*e3.w;

        uu  = u0.x*u0.x + u0.y*u0.y + u0.z*u0.z + u0.w*u0.w;
        uu += u1.x*u1.x + u1.y*u1.y + u1.z*u1.z + u1.w*u1.w;
        uu += u2.x*u2.x + u2.y*u2.y + u2.z*u2.z + u2.w*u2.w;
        uu += u3.x*u3.x + u3.y*u3.y + u3.z*u3.z + u3.w*u3.w;

        ee  = e0.x*e0.x + e0.y*e0.y + e0.z*e0.z + e0.w*e0.w;
        ee += e1.x*e1.x + e1.y*e1.y + e1.z*e1.z + e1.w*e1.w;
        ee += e2.x*e2.x + e2.y*e2.y + e2.z*e2.z + e2.w*e2.w;
        ee += e3.x*e3.x + e3.y*e3.y + e3.z*e3.z + e3.w*e3.w;

        uw  = u0.x*w0.x + u0.y*w0.y + u0.z*w0.z + u0.w*w0.w;
        uw += u1.x*w1.x + u1.y*w1.y + u1.z*w1.z + u1.w*w1.w;
        uw += u2.x*w2.x + u2.y*w2.y + u2.z*w2.z + u2.w*w2.w;
        uw += u3.x*w3.x + u3.y*w3.y + u3.z*w3.z + u3.w*w3.w;

        // Reduce across the 8-lane group (xor 4,2,1 stays within group):
        // 12 shuffles per warp serve 4 pairs.
        #pragma unroll
        for (int off = 4; off > 0; off >>= 1) {
            ue += __shfl_xor_sync(0xffffffffu, ue, off);
            uu += __shfl_xor_sync(0xffffffffu, uu, off);
            ee += __shfl_xor_sync(0xffffffffu, ee, off);
            uw += __shfl_xor_sync(0xffffffffu, uw, off);
        }

        if (sub == 0 && active) {
            const float un  = fmaxf(sqrtf(uu), EPS);
            const float en  = fmaxf(sqrtf(ee), EPS);
            const float sim = ue / (un * en);
            out[p] = fmaf(sim, wSim, uw + bias);
        }
    }
}

extern "C" void kernel_launch(void* const* d_in, const int* in_sizes, int n_in,
                              void* d_out, int out_size)
{
    const float* users  = (const float*)d_in[0];
    const float* events = (const float*)d_in[1];
    const int*   pu     = (const int*)d_in[2];
    const int*   pe     = (const int*)d_in[3];
    const int*   nu     = (const int*)d_in[4];
    const int*   ne     = (const int*)d_in[5];
    const float* W      = (const float*)d_in[6];
    const float* bb     = (const float*)d_in[7];
    float*       out    = (float*)d_out;

    const int P = in_sizes[2];                    // 524288 pairs
    const int blocks = NUM_SMS * BLOCKS_PER_SM;   // persistent: one resident wave

    uip_score_kernel<<<blocks, THREADS>>>(users, events, pu, pe, nu, ne, W, bb, out, P);
}

// round 6
// speedup vs baseline: 1.7270x; 1.2073x over previous
#include <cuda_runtime.h>
#include <cuda_bf16.h>

// Inputs (metadata order):
//  0: user_embeddings   [500000, 128] f32
//  1: event_embeddings  [100000, 128] f32
//  2: pos_user_idx      [P] i32
//  3: pos_event_idx     [P] i32
//  4: neg_user_idx      [P] i32
//  5: neg_event_idx     [P] i32
//  6: W                 [1, 129] f32
//  7: b                 [1] f32
// Output: [2, P] f32  (pos scores then neg scores)

#define EPS 1e-8f
#define NUM_SMS 148
#define BLOCKS_PER_SM 4
#define THREADS 256
#define WARPS_PER_BLOCK (THREADS / 32)

// 8 lanes cooperate per pair; 4 pairs per warp.
// DENSE coalescing: lane `sub` loads float4 at offsets {sub, sub+8, sub+16, sub+24}
// so each LDG.128 warp-instruction covers exactly one contiguous 128B line per pair.
__global__ __launch_bounds__(THREADS, BLOCKS_PER_SM) void uip_score_kernel(
    const float* __restrict__ users,
    const float* __restrict__ events,
    const int*   __restrict__ pu,
    const int*   __restrict__ pe,
    const int*   __restrict__ nu,
    const int*   __restrict__ ne,
    const float* __restrict__ W,
    const float* __restrict__ bb,
    float*       __restrict__ out,
    int P)
{
    const int lane = threadIdx.x & 31;
    const int sub  = lane & 7;     // position within 8-lane pair group
    const int grp  = lane >> 3;    // 0..3: which pair within the warp
    const int wid  = blockIdx.x * WARPS_PER_BLOCK + (threadIdx.x >> 5);
    const int nw   = gridDim.x * WARPS_PER_BLOCK;
    const int total = 2 * P;       // total pairs (pos then neg)

    // Per-warp invariants in registers: W slices at the SAME offsets as u loads.
    const float4 w0 = __ldg(reinterpret_cast<const float4*>(W) + sub + 0);
    const float4 w1 = __ldg(reinterpret_cast<const float4*>(W) + sub + 8);
    const float4 w2 = __ldg(reinterpret_cast<const float4*>(W) + sub + 16);
    const float4 w3 = __ldg(reinterpret_cast<const float4*>(W) + sub + 24);
    const float wSim = __ldg(W + 128);
    const float bias = __ldg(bb);

    const float4* u_tab = reinterpret_cast<const float4*>(users);
    const float4* e_tab = reinterpret_cast<const float4*>(events);

    const int n_iters = (total + 3) >> 2;   // total = 2^20, divisible by 4
    for (int i = wid; i < n_iters; i += nw) {
        const int p = i * 4 + grp;
        const bool active = (p < total);

        int ui = 0, ei = 0;
        if (active) {
            if (p < P) { ui = __ldg(pu + p);     ei = __ldg(pe + p); }
            else       { ui = __ldg(nu + p - P); ei = __ldg(ne + p - P); }
        }

        const float4* urow = u_tab + (size_t)ui * 32 + sub;
        const float4* erow = e_tab + (size_t)ei * 32 + sub;

        // 8 independent loads in flight per lane (MLP=8), each instruction
        // dense across the 8-lane group (1 line/pair/instruction).
        // User table (256MB, mostly DRAM): streaming -> don't pollute L2.
        // Event table (51MB, fits L2): default caching -> stays resident.
        const float4 u0 = __ldcs(urow + 0);
        const float4 u1 = __ldcs(urow + 8);
        const float4 u2 = __ldcs(urow + 16);
        const float4 u3 = __ldcs(urow + 24);
        const float4 e0 = __ldg(erow + 0);
        const float4 e1 = __ldg(erow + 8);
        const float4 e2 = __ldg(erow + 16);
        const float4 e3 = __ldg(erow + 24);

        float ue, uu, ee, uw;
        ue  = u0.x*e0.x + u0.y*e0.y + u0.z*e0.z + u0.w*e0.w;
        ue += u1.x*e1.x + u1.y*e1.y + u1.z*e1.z + u1.w*e1.w;
        ue += u2.x*e2.x + u2.y*e2.y + u2.z*e2.z + u2.w*e2.w;
        ue += u3.x*e3.x + u3.y*e3.y + u3.z*e3.z + u3.w*e3.w;

        uu  = u0.x*u0.x + u0.y*u0.y + u0.z*u0.z + u0.w*u0.w;
        uu += u1.x*u1.x + u1.y*u1.y + u1.z*u1.z + u1.w*u1.w;
        uu += u2.x*u2.x + u2.y*u2.y + u2.z*u2.z + u2.w*u2.w;
        uu += u3.x*u3.x + u3.y*u3.y + u3.z*u3.z + u3.w*u3.w;

        ee  = e0.x*e0.x + e0.y*e0.y + e0.z*e0.z + e0.w*e0.w;
        ee += e1.x*e1.x + e1.y*e1.y + e1.z*e1.z + e1.w*e1.w;
        ee += e2.x*e2.x + e2.y*e2.y + e2.z*e2.z + e2.w*e2.w;
        ee += e3.x*e3.x + e3.y*e3.y + e3.z*e3.z + e3.w*e3.w;

        uw  = u0.x*w0.x + u0.y*w0.y + u0.z*w0.z + u0.w*w0.w;
        uw += u1.x*w1.x + u1.y*w1.y + u1.z*w1.z + u1.w*w1.w;
        uw += u2.x*w2.x + u2.y*w2.y + u2.z*w2.z + u2.w*w2.w;
        uw += u3.x*w3.x + u3.y*w3.y + u3.z*w3.z + u3.w*w3.w;

        // Reduce across the 8-lane group (xor 4,2,1 stays within group):
        // 12 shuffles per warp serve 4 pairs.
        #pragma unroll
        for (int off = 4; off > 0; off >>= 1) {
            ue += __shfl_xor_sync(0xffffffffu, ue, off);
            uu += __shfl_xor_sync(0xffffffffu, uu, off);
            ee += __shfl_xor_sync(0xffffffffu, ee, off);
            uw += __shfl_xor_sync(0xffffffffu, uw, off);
        }

        if (sub == 0 && active) {
            const float un  = fmaxf(sqrtf(uu), EPS);
            const float en  = fmaxf(sqrtf(ee), EPS);
            const float sim = ue / (un * en);
            out[p] = fmaf(sim, wSim, uw + bias);
        }
    }
}

extern "C" void kernel_launch(void* const* d_in, const int* in_sizes, int n_in,
                              void* d_out, int out_size)
{
    const float* users  = (const float*)d_in[0];
    const float* events = (const float*)d_in[1];
    const int*   pu     = (const int*)d_in[2];
    const int*   pe     = (const int*)d_in[3];
    const int*   nu     = (const int*)d_in[4];
    const int*   ne     = (const int*)d_in[5];
    const float* W      = (const float*)d_in[6];
    const float* bb     = (const float*)d_in[7];
    float*       out    = (float*)d_out;

    const int P = in_sizes[2];                    // 524288 pairs
    const int blocks = NUM_SMS * BLOCKS_PER_SM;   // persistent: one resident wave

    uip_score_kernel<<<blocks, THREADS>>>(users, events, pu, pe, nu, ne, W, bb, out, P);
}

// round 7
// speedup vs baseline: 1.7529x; 1.0150x over previous
#include <cuda_runtime.h>
#include <cuda_bf16.h>

// Inputs (metadata order):
//  0: user_embeddings   [500000, 128] f32
//  1: event_embeddings  [100000, 128] f32
//  2: pos_user_idx      [P] i32
//  3: pos_event_idx     [P] i32
//  4: neg_user_idx      [P] i32
//  5: neg_event_idx     [P] i32
//  6: W                 [1, 129] f32
//  7: b                 [1] f32
// Output: [2, P] f32  (pos scores then neg scores)

#define EPS 1e-8f
#define NUM_SMS 148
#define BLOCKS_PER_SM 6
#define THREADS 256
#define WARPS_PER_BLOCK (THREADS / 32)

// 16 lanes cooperate per pair; 2 pairs per warp.
// Lane `sub` (0..15) loads float4 at offsets {sub, sub+16}: each LDG.128
// warp-instruction is dense (one contiguous 128B line per 8-lane half),
// and live vector state is only 6 float4 -> ~40 regs -> 6 blocks/SM.
__global__ __launch_bounds__(THREADS, BLOCKS_PER_SM) void uip_score_kernel(
    const float* __restrict__ users,
    const float* __restrict__ events,
    const int*   __restrict__ pu,
    const int*   __restrict__ pe,
    const int*   __restrict__ nu,
    const int*   __restrict__ ne,
    const float* __restrict__ W,
    const float* __restrict__ bb,
    float*       __restrict__ out,
    int P)
{
    const int lane = threadIdx.x & 31;
    const int sub  = lane & 15;    // position within 16-lane pair group
    const int grp  = lane >> 4;    // 0..1: which pair within the warp
    const int wid  = blockIdx.x * WARPS_PER_BLOCK + (threadIdx.x >> 5);
    const int nw   = gridDim.x * WARPS_PER_BLOCK;
    const int total = 2 * P;       // total pairs (pos then neg)

    // Per-warp invariants: this lane's W slice (8 elems), W[128], bias.
    const float4 w0 = __ldg(reinterpret_cast<const float4*>(W) + sub + 0);
    const float4 w1 = __ldg(reinterpret_cast<const float4*>(W) + sub + 16);
    const float wSim = __ldg(W + 128);
    const float bias = __ldg(bb);

    const float4* u_tab = reinterpret_cast<const float4*>(users);
    const float4* e_tab = reinterpret_cast<const float4*>(events);

    const int n_iters = (total + 1) >> 1;   // total = 2^20, divisible by 2
    for (int i = wid; i < n_iters; i += nw) {
        const int p = i * 2 + grp;
        const bool active = (p < total);

        int ui = 0, ei = 0;
        if (active) {
            if (p < P) { ui = __ldg(pu + p);     ei = __ldg(pe + p); }
            else       { ui = __ldg(nu + p - P); ei = __ldg(ne + p - P); }
        }

        const float4* urow = u_tab + (size_t)ui * 32 + sub;
        const float4* erow = e_tab + (size_t)ei * 32 + sub;

        // 4 independent loads in flight per lane; 16 DRAM lines/warp outstanding.
        // User table (256MB, streaming): __ldcs -> don't pollute L2.
        // Event table (51MB, L2-resident across graph replays): __ldg.
        const float4 u0 = __ldcs(urow + 0);
        const float4 u1 = __ldcs(urow + 16);
        const float4 e0 = __ldg(erow + 0);
        const float4 e1 = __ldg(erow + 16);

        float ue, uu, ee, uw;
        ue  = u0.x*e0.x + u0.y*e0.y + u0.z*e0.z + u0.w*e0.w;
        ue += u1.x*e1.x + u1.y*e1.y + u1.z*e1.z + u1.w*e1.w;

        uu  = u0.x*u0.x + u0.y*u0.y + u0.z*u0.z + u0.w*u0.w;
        uu += u1.x*u1.x + u1.y*u1.y + u1.z*u1.z + u1.w*u1.w;

        ee  = e0.x*e0.x + e0.y*e0.y + e0.z*e0.z + e0.w*e0.w;
        ee += e1.x*e1.x + e1.y*e1.y + e1.z*e1.z + e1.w*e1.w;

        uw  = u0.x*w0.x + u0.y*w0.y + u0.z*w0.z + u0.w*w0.w;
        uw += u1.x*w1.x + u1.y*w1.y + u1.z*w1.z + u1.w*w1.w;

        // Reduce across the 16-lane group (xor 8,4,2,1 stays within group):
        // 16 shuffles per warp serve 2 pairs.
        #pragma unroll
        for (int off = 8; off > 0; off >>= 1) {
            ue += __shfl_xor_sync(0xffffffffu, ue, off);
            uu += __shfl_xor_sync(0xffffffffu, uu, off);
            ee += __shfl_xor_sync(0xffffffffu, ee, off);
            uw += __shfl_xor_sync(0xffffffffu, uw, off);
        }

        if (sub == 0 && active) {
            const float un  = fmaxf(sqrtf(uu), EPS);
            const float en  = fmaxf(sqrtf(ee), EPS);
            const float sim = ue / (un * en);
            out[p] = fmaf(sim, wSim, uw + bias);
        }
    }
}

extern "C" void kernel_launch(void* const* d_in, const int* in_sizes, int n_in,
                              void* d_out, int out_size)
{
    const float* users  = (const float*)d_in[0];
    const float* events = (const float*)d_in[1];
    const int*   pu     = (const int*)d_in[2];
    const int*   pe     = (const int*)d_in[3];
    const int*   nu     = (const int*)d_in[4];
    const int*   ne     = (const int*)d_in[5];
    const float* W      = (const float*)d_in[6];
    const float* bb     = (const float*)d_in[7];
    float*       out    = (float*)d_out;

    const int P = in_sizes[2];                    // 524288 pairs
    const int blocks = NUM_SMS * BLOCKS_PER_SM;   // persistent: one resident wave

    uip_score_kernel<<<blocks, THREADS>>>(users, events, pu, pe, nu, ne, W, bb, out, P);
}